// round 2
// baseline (speedup 1.0000x reference)
#include <cuda_runtime.h>
#include <cuda_fp16.h>

#define NPTS   100000
#define BATCH  16
#define MNB    9
#define NSLOTS (NPTS * 3)            /* 300000 per-batch floats   */
#define NELEM  (NPTS * 48)           /* total diff elements, 4.8M */
#define ROWH2  24                    /* half2 per point row        */
#define PTS_PER_BLK 8                /* warps per block in k_lap   */
#define NBLK2 (NPTS / PTS_PER_BLK)   /* 12500, exact               */

// Scratch: d = gt - pr in fp16, layout (n, c, b): g_dt[n*48 + c*16 + b]
__device__ __half g_dt[NELEM];
__device__ float  g_partial[NBLK2];

// ---------------------------------------------------------------------------
// Kernel 1: diff + transpose, no smem. Output linear index IS n*48+c*16+b
// because idx = slot*16 + b with slot = n*3+c. Writes fully coalesced (64B
// of half per warp); reads hit 16 sectors/warp with 4x L1 reuse in-block.
// ---------------------------------------------------------------------------
__global__ void k_diff(const float* __restrict__ gt, const float* __restrict__ pr) {
    int idx  = blockIdx.x * 256 + threadIdx.x;   // grid sized exactly NELEM/256
    int b    = idx & 15;
    int slot = idx >> 4;                         // n*3 + c
    int gi   = b * NSLOTS + slot;
    float v  = __ldg(gt + gi) - __ldg(pr + gi);
    g_dt[idx] = __float2half_rn(v);
}

// ---------------------------------------------------------------------------
// Kernel 2: one warp per point. Lanes 0..23 each own one half2 slot of the
// 96B row (fixed (c, batch-pair) position — identical across all rows, so
// the laplacian is computed slot-wise). 9 gathers of 96B per point.
// Deterministic fixed-order reductions, no float atomics.
// ---------------------------------------------------------------------------
__global__ void k_lap(const int* __restrict__ nb, const float* __restrict__ num) {
    const unsigned FULL = 0xFFFFFFFFu;
    int tid  = threadIdx.x;
    int lane = tid & 31;
    int n    = blockIdx.x * PTS_PER_BLK + (tid >> 5);   // always < NPTS (exact)

    int myid = (lane < MNB) ? nb[n * MNB + lane] : 0;
    float wnum = num[n];
    bool act = (lane < ROWH2);
    const __half2* dt2 = (const __half2*)g_dt;

    // center (column 0) — reference uses it unconditionally (zero row if ==N)
    int id0 = __shfl_sync(FULL, myid, 0);
    float ax = 0.0f, ay = 0.0f;
    if (act && id0 < NPTS) {
        __half2 h = dt2[(size_t)id0 * ROWH2 + lane];
        float2 f = __half22float2(h);
        ax = f.x * wnum;
        ay = f.y * wnum;
    }

    #pragma unroll
    for (int j = 1; j < MNB; j++) {
        int idj = __shfl_sync(FULL, myid, j);
        if (idj < NPTS && act) {
            __half2 h = dt2[(size_t)idj * ROWH2 + lane];
            float2 f = __half22float2(h);
            ax -= f.x;
            ay -= f.y;
        }
    }

    float acc = act ? (fabsf(ax) + fabsf(ay)) : 0.0f;

    // warp reduce (fixed order -> deterministic)
    #pragma unroll
    for (int off = 16; off > 0; off >>= 1)
        acc += __shfl_down_sync(FULL, acc, off);

    __shared__ float ws[PTS_PER_BLK];
    if (lane == 0) ws[tid >> 5] = acc;
    __syncthreads();
    if (tid < PTS_PER_BLK) {
        float v = ws[tid];
        #pragma unroll
        for (int off = PTS_PER_BLK / 2; off > 0; off >>= 1)
            v += __shfl_down_sync((1u << PTS_PER_BLK) - 1u, v, off);
        if (tid == 0) g_partial[blockIdx.x] = v;
    }
}

// ---------------------------------------------------------------------------
// Kernel 3: deterministic final reduction + mean
// ---------------------------------------------------------------------------
__global__ void k_reduce(float* __restrict__ out) {
    __shared__ float s[1024];
    float v = 0.0f;
    for (int i = threadIdx.x; i < NBLK2; i += 1024)
        v += g_partial[i];
    s[threadIdx.x] = v;
    __syncthreads();
    #pragma unroll
    for (int off = 512; off > 0; off >>= 1) {
        if (threadIdx.x < off) s[threadIdx.x] += s[threadIdx.x + off];
        __syncthreads();
    }
    if (threadIdx.x == 0)
        out[0] = s[0] * (1.0f / (float)(BATCH * NPTS * 3));
}

// ---------------------------------------------------------------------------
extern "C" void kernel_launch(void* const* d_in, const int* in_sizes, int n_in,
                              void* d_out, int out_size) {
    const float* gt  = (const float*)d_in[0];   // gt_pc        (B,N,3) f32
    const float* pr  = (const float*)d_in[1];   // predict_pc   (B,N,3) f32
    const int*   nb  = (const int*)  d_in[2];   // neighbor ids (N,9)   i32
    const float* num = (const float*)d_in[3];   // neighbor_num (N,)    f32
    float* out = (float*)d_out;

    k_diff  <<<NELEM / 256, 256>>>(gt, pr);     // 18750 blocks, exact
    k_lap   <<<NBLK2, 256>>>(nb, num);          // 12500 blocks, exact
    k_reduce<<<1, 1024>>>(out);
}

// round 3
// speedup vs baseline: 1.1509x; 1.1509x over previous
#include <cuda_runtime.h>

#define NPTS   100000
#define BATCH  16
#define MNB    9
#define NSLOTS (NPTS * 3)            /* per-batch floats           */
#define TP     64                    /* points per transpose tile  */
#define PTS_PER_BLK2 16
#define NBLK2  (NPTS / PTS_PER_BLK2) /* 6250, exact                */
#define INV_COUNT (1.0f / (float)(BATCH * NPTS * 3))

// Scratch: d = gt - pr, layout (n, c, b): g_dt[n*48 + c*16 + b], fp32
__device__ float g_dt[NPTS * 48];

// bank-conflict-free swizzle of batch index for slot r
__device__ __forceinline__ int swz(int b, int r) {
    return b ^ ((r ^ (r >> 4)) & 15);
}

// ---------------------------------------------------------------------------
// Kernel 1: diff + transpose (B,N,3) -> (N,3,B) via swizzled smem.
// Reads coalesced per-batch segments; smem writes/reads conflict-free;
// global writes fully contiguous. Also zeroes out[0] for k_lap's atomics.
// ---------------------------------------------------------------------------
__global__ void k_diff(const float* __restrict__ gt, const float* __restrict__ pr,
                       float* __restrict__ out) {
    if (blockIdx.x == 0 && threadIdx.x == 0) out[0] = 0.0f;

    __shared__ float s[TP * 48];
    int n0 = blockIdx.x * TP;
    int base_slot = n0 * 3;

    // Load: i = (b, r) with r contiguous per b -> coalesced global reads.
    // Smem write: fixed b, consecutive r -> 32 distinct banks (swizzled).
    for (int i = threadIdx.x; i < TP * 48; i += 256) {
        int b = i / (TP * 3);
        int r = i % (TP * 3);
        int slot = base_slot + r;
        float v = 0.0f;
        if (slot < NSLOTS) {
            int gi = b * NSLOTS + slot;
            v = __ldg(gt + gi) - __ldg(pr + gi);
        }
        s[r * 16 + swz(b, r)] = v;
    }
    __syncthreads();

    // Store: output [n0*48 .. ) contiguous; smem read conflict-free.
    int valid = NPTS - n0;
    if (valid > TP) valid = TP;
    int total = valid * 48;
    int obase = n0 * 48;
    for (int j = threadIdx.x; j < total; j += 256) {
        int r = j >> 4;
        int b = j & 15;
        g_dt[obase + j] = s[(r << 4) + swz(b, r)];
    }
}

// ---------------------------------------------------------------------------
// Kernel 2 (R1-proven structure): 16 lanes = 16 batches per point,
// 256 threads = 16 points/block. Per-block deterministic reduce, then one
// pre-scaled atomicAdd per block into out[0].
// ---------------------------------------------------------------------------
__global__ void k_lap(const int* __restrict__ nb, const float* __restrict__ num,
                      float* __restrict__ out) {
    int tid  = threadIdx.x;
    int lane = tid & 15;          // batch index
    int n    = blockIdx.x * PTS_PER_BLK2 + (tid >> 4);   // exact grid, n < NPTS

    int myid = (lane < MNB) ? nb[n * MNB + lane] : 0;
    float wnum = num[n];

    const unsigned FULL = 0xFFFFFFFFu;
    int id0 = __shfl_sync(FULL, myid, 0, 16);
    int id1 = __shfl_sync(FULL, myid, 1, 16);
    int id2 = __shfl_sync(FULL, myid, 2, 16);
    int id3 = __shfl_sync(FULL, myid, 3, 16);
    int id4 = __shfl_sync(FULL, myid, 4, 16);
    int id5 = __shfl_sync(FULL, myid, 5, 16);
    int id6 = __shfl_sync(FULL, myid, 6, 16);
    int id7 = __shfl_sync(FULL, myid, 7, 16);
    int id8 = __shfl_sync(FULL, myid, 8, 16);

    const float* pc = g_dt + (size_t)id0 * 48 + lane;
    float c0 = pc[0]  * wnum;
    float c1 = pc[16] * wnum;
    float c2 = pc[32] * wnum;

#define SUB_NB(idj)                                                \
    if ((idj) < NPTS) {                                            \
        const float* p_ = g_dt + (size_t)(idj) * 48 + lane;        \
        c0 -= p_[0]; c1 -= p_[16]; c2 -= p_[32];                   \
    }
    SUB_NB(id1) SUB_NB(id2) SUB_NB(id3) SUB_NB(id4)
    SUB_NB(id5) SUB_NB(id6) SUB_NB(id7) SUB_NB(id8)
#undef SUB_NB

    float acc = fabsf(c0) + fabsf(c1) + fabsf(c2);

    // warp reduce (fixed order)
    #pragma unroll
    for (int off = 16; off > 0; off >>= 1)
        acc += __shfl_down_sync(FULL, acc, off);

    __shared__ float ws[8];
    if ((tid & 31) == 0) ws[tid >> 5] = acc;
    __syncthreads();
    if (tid < 8) {
        float v = ws[tid];
        #pragma unroll
        for (int off = 4; off > 0; off >>= 1)
            v += __shfl_down_sync(0xFFu, v, off);
        if (tid == 0)
            atomicAdd(out, v * INV_COUNT);
    }
}

// ---------------------------------------------------------------------------
extern "C" void kernel_launch(void* const* d_in, const int* in_sizes, int n_in,
                              void* d_out, int out_size) {
    const float* gt  = (const float*)d_in[0];   // gt_pc        (B,N,3) f32
    const float* pr  = (const float*)d_in[1];   // predict_pc   (B,N,3) f32
    const int*   nb  = (const int*)  d_in[2];   // neighbor ids (N,9)   i32
    const float* num = (const float*)d_in[3];   // neighbor_num (N,)    f32
    float* out = (float*)d_out;

    int nblk1 = (NPTS + TP - 1) / TP;           // 1563
    k_diff<<<nblk1, 256>>>(gt, pr, out);
    k_lap <<<NBLK2, 256>>>(nb, num, out);
}

// round 5
// speedup vs baseline: 1.5987x; 1.3890x over previous
#include <cuda_runtime.h>
#include <cuda_fp16.h>

#define NPTS   100000
#define BATCH  16
#define MNB    9
#define NSLOTS (NPTS * 3)              /* per-batch floats, divisible by 4 */
#define TP     128                     /* points per k_diff tile           */
#define QB     (TP * 3 / 4)            /* 96 float4 slots per batch        */
#define LAP_BLOCKS (NPTS / 40)         /* 2500: 8 warps x 5 pts, exact     */
#define INV_COUNT (1.0f / (float)(BATCH * NPTS * 3))

// Scratch: d = gt - pr in fp16, row layout g_dt[n*48 + c*16 + b]
__device__ __half g_dt[NPTS * 48];

// ---------------------------------------------------------------------------
// Kernel 1: diff + transpose (B,N,3) -> rows of 48 halves per point.
// float4 global loads, conflict-free swizzled float4 smem, half2 stores.
// ---------------------------------------------------------------------------
__global__ void k_diff(const float* __restrict__ gt, const float* __restrict__ pr,
                       float* __restrict__ out) {
    if (blockIdx.x == 0 && threadIdx.x == 0) out[0] = 0.0f;

    __shared__ float4 s4[QB * 16];     // 24KB
    const float* sf = (const float*)s4;

    int n0 = blockIdx.x * TP;
    int slot0 = n0 * 3;

    // Load phase: i = b*QB + q. Within b, consecutive lanes -> consecutive
    // float4 (coalesced 512B/warp). smem write bank = 4*((b&7)^(q&7)):
    // 8 distinct banks per 8-lane phase -> conflict-free.
    for (int i = threadIdx.x; i < 16 * QB; i += 256) {
        int b = i / QB;
        int q = i - b * QB;
        int slot = slot0 + q * 4;
        float4 v = make_float4(0.f, 0.f, 0.f, 0.f);
        if (slot < NSLOTS) {           // NSLOTS % 4 == 0: never partial
            float4 g = *(const float4*)(gt + (size_t)b * NSLOTS + slot);
            float4 p = *(const float4*)(pr + (size_t)b * NSLOTS + slot);
            v = make_float4(g.x - p.x, g.y - p.y, g.z - p.z, g.w - p.w);
        }
        s4[q * 16 + (b ^ (q & 15))] = v;
    }
    __syncthreads();

    // Store phase: half2 j covers halves m=2j,2j+1: (r = m>>4, b = m&15).
    // Output global half index = n0*48 + m = n*48 + c*16 + b (fixed perm).
    int valid = NPTS - n0;
    if (valid > TP) valid = TP;
    int total2 = valid * 24;           // half2 per tile
    __half2* outp = (__half2*)g_dt + (size_t)n0 * 24;
    for (int j = threadIdx.x; j < total2; j += 256) {
        int m  = 2 * j;
        int r  = m >> 4;
        int b0 = m & 15;               // even
        int q  = r >> 2;
        int cmp = r & 3;
        float f0 = sf[4 * (q * 16 + (b0       ^ (q & 15))) + cmp];
        float f1 = sf[4 * (q * 16 + ((b0 + 1) ^ (q & 15))) + cmp];
        outp[j] = __floats2half2_rn(f0, f1);
    }
}

// ---------------------------------------------------------------------------
// Kernel 2: gather laplacian. 5 points per warp, 6 lanes per point, each
// lane owns one 16B chunk (8 halves) of the 96B row. One LDG.128 per warp
// per neighbor step. Neighbors accumulated in half2; center term in fp32.
// ---------------------------------------------------------------------------
__global__ void k_lap(const int* __restrict__ nb, const float* __restrict__ num,
                      float* __restrict__ out) {
    const unsigned FULL = 0xFFFFFFFFu;
    int tid  = threadIdx.x;
    int lane = tid & 31;
    int wp   = blockIdx.x * 8 + (tid >> 5);      // 20000 warps total
    int g    = lane / 6;                          // point group 0..4 (5: idle)
    int s    = lane - g * 6;                      // chunk 0..5
    bool act = lane < 30;
    int n    = wp * 5 + (act ? g : 0);            // n < NPTS when act

    int idA = 0, idB = 0;
    float wnum = 0.0f;
    if (act) {
        idA = nb[n * MNB + s];                    // neighbor s (s<6)
        if (s < 3) idB = nb[n * MNB + 6 + s];     // neighbors 6..8
        wnum = num[n];
    }
    const char* base = (const char*)g_dt;
    int coff = s * 16;                            // byte offset of my chunk

    // center (neighbor index 0) in fp32
    float c[8];
    {
        int id0 = __shfl_sync(FULL, idA, (g % 5) * 6);
        #pragma unroll
        for (int k = 0; k < 8; k++) c[k] = 0.0f;
        if (act && id0 < NPTS) {
            uint4 v = *(const uint4*)(base + (size_t)id0 * 96 + coff);
            const __half2* h = (const __half2*)&v;
            #pragma unroll
            for (int k = 0; k < 4; k++) {
                float2 f = __half22float2(h[k]);
                c[2 * k]     = f.x * wnum;
                c[2 * k + 1] = f.y * wnum;
            }
        }
    }

    // neighbors 1..8 accumulated in half2
    __half2 hacc[4];
    #pragma unroll
    for (int k = 0; k < 4; k++) hacc[k] = __float2half2_rn(0.0f);

    #pragma unroll
    for (int j = 1; j < MNB; j++) {
        int src = (g % 5) * 6 + (j < 6 ? j : (j - 6));
        int idj = __shfl_sync(FULL, (j < 6 ? idA : idB), src);
        if (act && idj < NPTS) {
            uint4 v = *(const uint4*)(base + (size_t)idj * 96 + coff);
            const __half2* h = (const __half2*)&v;
            #pragma unroll
            for (int k = 0; k < 4; k++) hacc[k] = __hadd2(hacc[k], h[k]);
        }
    }

    float acc = 0.0f;
    if (act) {
        #pragma unroll
        for (int k = 0; k < 4; k++) {
            float2 f = __half22float2(hacc[k]);
            acc += fabsf(c[2 * k] - f.x) + fabsf(c[2 * k + 1] - f.y);
        }
    }

    // warp reduce (fixed order), then block reduce, one atomic per block
    #pragma unroll
    for (int off = 16; off > 0; off >>= 1)
        acc += __shfl_down_sync(FULL, acc, off);

    __shared__ float ws[8];
    if (lane == 0) ws[tid >> 5] = acc;
    __syncthreads();
    if (tid < 8) {
        float v = ws[tid];
        #pragma unroll
        for (int off = 4; off > 0; off >>= 1)
            v += __shfl_down_sync(0xFFu, v, off);
        if (tid == 0)
            atomicAdd(out, v * INV_COUNT);
    }
}

// ---------------------------------------------------------------------------
extern "C" void kernel_launch(void* const* d_in, const int* in_sizes, int n_in,
                              void* d_out, int out_size) {
    const float* gt  = (const float*)d_in[0];   // gt_pc        (B,N,3) f32
    const float* pr  = (const float*)d_in[1];   // predict_pc   (B,N,3) f32
    const int*   nb  = (const int*)  d_in[2];   // neighbor ids (N,9)   i32
    const float* num = (const float*)d_in[3];   // neighbor_num (N,)    f32
    float* out = (float*)d_out;

    int nblk1 = (NPTS + TP - 1) / TP;           // 782
    k_diff<<<nblk1, 256>>>(gt, pr, out);
    k_lap <<<LAP_BLOCKS, 256>>>(nb, num, out);
}

// round 7
// speedup vs baseline: 2.4088x; 1.5068x over previous
#include <cuda_runtime.h>
#include <cuda_fp16.h>

#define NPTS   100000
#define BATCH  16
#define MNB    9
#define NSLOTS (NPTS * 3)              /* per-batch floats, divisible by 4 */
#define TP     128                     /* points per k_diff tile           */
#define QB     (TP * 3 / 4)            /* 96 float4 slots per batch        */
#define ROWB   128                     /* padded row bytes (data in 96B)   */
#define LAP_BLOCKS (NPTS / 40)         /* 2500: 8 warps x 5 pts, exact     */
#define INV_COUNT (1.0f / (float)(BATCH * NPTS * 3))

// Scratch: d = gt - pr in fp16. Row n at byte n*128; halves [0,48) hold
// value at (c,b) packed as index c*16+b. Bytes [96,128) are padding.
__device__ __half g_dt[NPTS * 64];

// ---------------------------------------------------------------------------
// Kernel 1: diff + transpose (B,N,3) -> padded fp16 rows.
// float4 global loads, conflict-free swizzled float4 smem, half2 stores.
// ---------------------------------------------------------------------------
__global__ void k_diff(const float* __restrict__ gt, const float* __restrict__ pr,
                       float* __restrict__ out) {
    if (blockIdx.x == 0 && threadIdx.x == 0) out[0] = 0.0f;

    __shared__ float4 s4[QB * 16];     // 24KB
    const float* sf = (const float*)s4;

    int n0 = blockIdx.x * TP;
    int slot0 = n0 * 3;

    // Load phase: i = b*QB + q. Within b, consecutive lanes -> consecutive
    // float4 (coalesced 512B/warp). smem bank = 4*((b&7)^(q&7)): conflict-free.
    for (int i = threadIdx.x; i < 16 * QB; i += 256) {
        int b = i / QB;
        int q = i - b * QB;
        int slot = slot0 + q * 4;
        float4 v = make_float4(0.f, 0.f, 0.f, 0.f);
        if (slot < NSLOTS) {           // NSLOTS % 4 == 0: never partial
            float4 g = *(const float4*)(gt + (size_t)b * NSLOTS + slot);
            float4 p = *(const float4*)(pr + (size_t)b * NSLOTS + slot);
            v = make_float4(g.x - p.x, g.y - p.y, g.z - p.z, g.w - p.w);
        }
        s4[q * 16 + (b ^ (q & 15))] = v;
    }
    __syncthreads();

    // Store phase: j-th half2 of the tile payload (24 per point).
    // m = 2j: r = m>>4 (slot in tile = p*3+c), b0 = m&15.
    int valid = NPTS - n0;
    if (valid > TP) valid = TP;
    int total2 = valid * 24;
    __half2* outp = (__half2*)g_dt;
    for (int j = threadIdx.x; j < total2; j += 256) {
        int m   = 2 * j;
        int r   = m >> 4;              // slot index within tile
        int b0  = m & 15;              // even batch
        int q   = r >> 2;
        int cmp = r & 3;
        float f0 = sf[4 * (q * 16 + (b0       ^ (q & 15))) + cmp];
        float f1 = sf[4 * (q * 16 + ((b0 + 1) ^ (q & 15))) + cmp];
        int p = r / 3, c = r - 3 * p;  // point-in-tile, component
        int hidx = (n0 + p) * 64 + c * 16 + b0;   // half index, even
        outp[hidx >> 1] = __floats2half2_rn(f0, f1);
    }
}

// ---------------------------------------------------------------------------
// Kernel 2: gather laplacian. 5 points/warp, 6 lanes/point, lane owns one
// line-aligned 16B chunk of the 128B row. Each lane loads its own 9 ids
// (broadcast within group) -> no shfl dependency; 9 independent gathers.
// Dual half2 accumulator chains; center term in fp32.
// ---------------------------------------------------------------------------
__global__ void __launch_bounds__(256)
k_lap(const int* __restrict__ nb, const float* __restrict__ num,
      float* __restrict__ out) {
    const unsigned FULL = 0xFFFFFFFFu;
    int tid  = threadIdx.x;
    int lane = tid & 31;
    int wp   = blockIdx.x * 8 + (tid >> 5);
    int g    = lane / 6;                          // point group 0..4 (5: idle)
    int s    = lane - g * 6;                      // chunk 0..5
    bool act = lane < 30;
    int n    = wp * 5 + (act ? g : 0);

    int ids[MNB];
    #pragma unroll
    for (int j = 0; j < MNB; j++)
        ids[j] = act ? __ldg(nb + n * MNB + j) : NPTS;
    float wnum = act ? __ldg(num + n) : 0.0f;

    const char* base = (const char*)g_dt;
    int coff = s * 16;

    // all 9 row chunks, independent loads (MLP=9)
    uint4 v[MNB];
    const uint4 z4 = make_uint4(0u, 0u, 0u, 0u);
    #pragma unroll
    for (int j = 0; j < MNB; j++)
        v[j] = (ids[j] < NPTS)
             ? *(const uint4*)(base + (size_t)ids[j] * ROWB + coff)
             : z4;

    // center in fp32
    float c[8];
    {
        const __half2* h = (const __half2*)&v[0];
        #pragma unroll
        for (int k = 0; k < 4; k++) {
            float2 f = __half22float2(h[k]);
            c[2 * k]     = f.x * wnum;
            c[2 * k + 1] = f.y * wnum;
        }
    }

    // neighbors 1..8: two independent half2 chains
    __half2 ha[4], hb[4];
    #pragma unroll
    for (int k = 0; k < 4; k++) { ha[k] = __float2half2_rn(0.0f); hb[k] = ha[k]; }
    #pragma unroll
    for (int j = 1; j < MNB; j += 2) {
        const __half2* h = (const __half2*)&v[j];
        #pragma unroll
        for (int k = 0; k < 4; k++) ha[k] = __hadd2(ha[k], h[k]);
    }
    #pragma unroll
    for (int j = 2; j < MNB; j += 2) {
        const __half2* h = (const __half2*)&v[j];
        #pragma unroll
        for (int k = 0; k < 4; k++) hb[k] = __hadd2(hb[k], h[k]);
    }

    float acc = 0.0f;
    if (act) {
        #pragma unroll
        for (int k = 0; k < 4; k++) {
            float2 fa = __half22float2(ha[k]);
            float2 fb = __half22float2(hb[k]);
            acc += fabsf(c[2 * k]     - fa.x - fb.x)
                 + fabsf(c[2 * k + 1] - fa.y - fb.y);
        }
    }

    // warp reduce (fixed order), block reduce, one atomic per block
    #pragma unroll
    for (int off = 16; off > 0; off >>= 1)
        acc += __shfl_down_sync(FULL, acc, off);

    __shared__ float ws[8];
    if (lane == 0) ws[tid >> 5] = acc;
    __syncthreads();
    if (tid < 8) {
        float w = ws[tid];
        #pragma unroll
        for (int off = 4; off > 0; off >>= 1)
            w += __shfl_down_sync(0xFFu, w, off);
        if (tid == 0)
            atomicAdd(out, w * INV_COUNT);
    }
}

// ---------------------------------------------------------------------------
extern "C" void kernel_launch(void* const* d_in, const int* in_sizes, int n_in,
                              void* d_out, int out_size) {
    const float* gt  = (const float*)d_in[0];   // gt_pc        (B,N,3) f32
    const float* pr  = (const float*)d_in[1];   // predict_pc   (B,N,3) f32
    const int*   nb  = (const int*)  d_in[2];   // neighbor ids (N,9)   i32
    const float* num = (const float*)d_in[3];   // neighbor_num (N,)    f32
    float* out = (float*)d_out;

    int nblk1 = (NPTS + TP - 1) / TP;           // 782
    k_diff<<<nblk1, 256>>>(gt, pr, out);
    k_lap <<<LAP_BLOCKS, 256>>>(nb, num, out);
}